// round 6
// baseline (speedup 1.0000x reference)
#include <cuda_runtime.h>
#include <math.h>

#define T_TOK 8192
#define NH 16
#define HD 128
#define CH 64
#define NC 128
#define ROW (NH*HD)   // 2048

// ------------------- device scratch (allocation-free) -------------------
__device__ float gq [T_TOK*ROW];   // q      -> q~ (phase2)
__device__ float gk [T_TOK*ROW];   // k      -> Kbar
__device__ float gv [T_TOK*ROW];   // v      -> Vb
__device__ float gg [T_TOK*ROW];   // g(log) -> Kb
__device__ float gb [T_TOK*NH];
__device__ float gM [NC*NH*CH*CH];
__device__ float gCp[NC*NH*HD];

// =========================================================================
// Phase 1: conv(K=4)+SiLU, l2norm q/k, gates
// grid (NC, NH), block 128 (= d)
// =========================================================================
__global__ void __launch_bounds__(128) k_phase1(
    const float* __restrict__ qkv, const float* __restrict__ fg,
    const float* __restrict__ beta, const float* __restrict__ cw,
    const float* __restrict__ dtb, const float* __restrict__ alog)
{
    int h = blockIdx.y, t0 = blockIdx.x * CH, d = threadIdx.x;
    int cq = h*HD + d, ck = ROW + cq, cv = 2*ROW + cq;
    float wq[4], wk[4], wv[4];
#pragma unroll
    for (int j = 0; j < 4; ++j) {
        wq[j] = cw[cq*4 + j];
        wk[j] = cw[ck*4 + j];
        wv[j] = cw[cv*4 + j];
    }
    float ea  = expf(alog[h]);
    float dtv = dtb[h*HD + d];
    __shared__ float red[8];
    int wid = d >> 5, lid = d & 31;

    for (int tt = 0; tt < CH; ++tt) {
        int t = t0 + tt;
        float xq = 0.f, xk = 0.f, xv = 0.f;
#pragma unroll
        for (int j = 0; j < 4; ++j) {
            int ts = t - 3 + j;
            if (ts >= 0) {
                const float* row = qkv + (size_t)ts * (3*ROW);
                xq += row[cq] * wq[j];
                xk += row[ck] * wk[j];
                xv += row[cv] * wv[j];
            }
        }
        // SiLU
        xq = xq / (1.f + __expf(-xq));
        xk = xk / (1.f + __expf(-xk));
        xv = xv / (1.f + __expf(-xv));
        // block reduce q^2, k^2
        float sq = xq*xq, sk = xk*xk;
#pragma unroll
        for (int m = 16; m; m >>= 1) {
            sq += __shfl_xor_sync(~0u, sq, m);
            sk += __shfl_xor_sync(~0u, sk, m);
        }
        if (lid == 0) { red[wid] = sq; red[4+wid] = sk; }
        __syncthreads();
        float tq  = red[0]+red[1]+red[2]+red[3];
        float tk2 = red[4]+red[5]+red[6]+red[7];
        __syncthreads();
        float qn = xq * rsqrtf(tq  + 1e-6f) * 0.08838834764831845f; // D^-1/2
        float kn = xk * rsqrtf(tk2 + 1e-6f);
        // gate: g = -exp(alog)*softplus(fg + dt_bias)
        float gr = fg[(size_t)t*ROW + h*HD + d] + dtv;
        float sp = (gr > 20.f) ? gr : log1pf(__expf(gr));
        float gl = -ea * sp;
        size_t o = ((size_t)t*NH + h)*HD + d;
        gq[o] = qn; gk[o] = kn; gv[o] = xv; gg[o] = gl;
        if (d == 0) {
            float bb = beta[t*NH + h];
            gb[t*NH + h] = 1.f / (1.f + __expf(-bb));
        }
    }
}

// =========================================================================
// Phase 2: per (chunk, head) tile. gc cumsum, pair matrices A/M,
// forward substitution (I+L)^{-1} [b*v | b*k~] -> Vb, Kb.
// grid (NC, NH), block 256, dyn smem 113 KB
// =========================================================================
__global__ void __launch_bounds__(256) k_phase2()
{
    extern __shared__ float sm[];
    float* gcS = sm;               // 64*129 (later ZB = Kb)
    float* qS  = gcS + 64*129;     // 64*129 (later ZA = Vb)
    float* kS  = qS  + 64*129;     // 64*129
    float* Ls  = kS  + 64*129;     // 64*64
    float* bS  = Ls  + 64*64;      // 64

    int c = blockIdx.x, h = blockIdx.y, tid = threadIdx.x;
    size_t tbase = ((size_t)c*CH*NH + h)*HD;   // (t=c*64, h, 0); row stride ROW

    for (int i = tid; i < CH*HD; i += 256) {
        int t = i >> 7, k = i & 127;
        size_t go = tbase + (size_t)t*ROW + k;
        gcS[t*129+k] = gg[go];
        qS [t*129+k] = gq[go];
        kS [t*129+k] = gk[go];
    }
    if (tid < CH) bS[tid] = gb[(c*CH + tid)*NH + h];
    __syncthreads();

    // gc cumulative sum along t (inclusive)
    if (tid < HD) {
        float run = 0.f;
        for (int t = 0; t < CH; ++t) { run += gcS[t*129+tid]; gcS[t*129+tid] = run; }
    }
    __syncthreads();

    // write q~ = q*exp(gc), Kbar = k*exp(gc63-gc), cp = exp(gc63)
    for (int i = tid; i < CH*HD; i += 256) {
        int t = i >> 7, k = i & 127;
        float gct = gcS[t*129+k];
        float g63 = gcS[63*129+k];
        size_t go = tbase + (size_t)t*ROW + k;
        gq[go] = qS[t*129+k] * __expf(gct);
        gk[go] = kS[t*129+k] * __expf(g63 - gct);
    }
    if (tid < HD) gCp[(c*NH+h)*HD + tid] = __expf(gcS[63*129+tid]);

    // pair loop: A[t][s] (s<t) -> L, M[t][s] (s<=t) -> global
    size_t mbase = (size_t)(c*NH + h) * CH * CH;
    for (int p = tid; p < 2080; p += 256) {
        int t = (int)((sqrtf(8.f*p + 1.f) - 1.f) * 0.5f);
        while ((t+1)*(t+2)/2 <= p) ++t;
        while (t*(t+1)/2 > p) --t;
        int s = p - t*(t+1)/2;
        const float* gt = gcS + t*129; const float* gs = gcS + s*129;
        const float* kt = kS  + t*129; const float* ksr = kS + s*129;
        const float* qt = qS  + t*129;
        float a = 0.f, m = 0.f;
#pragma unroll 4
        for (int k = 0; k < HD; ++k) {
            float e  = __expf(gt[k] - gs[k]);   // exponent <= 0 : safe
            float kv = ksr[k] * e;
            a += kt[k]*kv;
            m += qt[k]*kv;
        }
        gM[mbase + t*64 + s] = m;
        if (s < t) Ls[t*64 + s] = bS[t] * a;
    }
    // zero upper triangle of M
    for (int i = tid; i < 4096; i += 256) {
        int t = i >> 6, s = i & 63;
        if (s > t) gM[mbase + i] = 0.f;
    }
    __syncthreads();

    // Z init (in place): ZA(qS) = b*v, ZB(gcS) = b*k*exp(gc)
    for (int i = tid; i < CH*HD; i += 256) {
        int t = i >> 7, k = i & 127;
        size_t go = tbase + (size_t)t*ROW + k;
        float bb = bS[t];
        qS [t*129+k] = bb * gv[go];
        gcS[t*129+k] = bb * kS[t*129+k] * __expf(gcS[t*129+k]);
    }
    __syncthreads();

    // forward substitution (I+L) Z = RHS  — per column independent, no syncs
    {
        float* Z = (tid < 128) ? qS : gcS;
        int col = tid & 127;
        for (int t = 1; t < CH; ++t) {
            float acc = 0.f;
            const float* lrow = Ls + t*64;
            for (int s = 0; s < t; ++s) acc += lrow[s] * Z[s*129 + col];
            Z[t*129 + col] -= acc;
        }
    }
    __syncthreads();

    // write out: Vb -> gv, Kb -> gg
    for (int i = tid; i < CH*HD; i += 256) {
        int t = i >> 7, k = i & 127;
        size_t go = tbase + (size_t)t*ROW + k;
        gv[go] = qS [t*129+k];
        gg[go] = gcS[t*129+k];
    }
}

// =========================================================================
// Phase 3: sequential chunk scan. grid (8, NH) = 128 blocks, 512 thr.
// Per chunk:  D = Vb - Kb@S ; O = Qt@S + M@D ; S = cp.*S + Kbar^T@D
// =========================================================================
__global__ void __launch_bounds__(512) k_phase3(float* __restrict__ out)
{
    extern __shared__ float sm[];
    float* KbS = sm;               // 64*129
    float* QtS = KbS + 64*129;
    float* KrS = QtS + 64*129;
    float* MS  = KrS + 64*129;     // 64*65
    float* VbS = MS  + 64*65;      // 64*16
    float* DS  = VbS + 1024;       // 64*16
    float* cpS = DS  + 1024;       // 128
    float* S   = cpS + 128;        // 128*16

    int h = blockIdx.y, j0 = blockIdx.x * 16, tid = threadIdx.x;
    int t  = tid >> 3, kq = tid & 7, k0 = kq * 16;
    int krow = tid >> 2, jq = tid & 3;

    for (int i = tid; i < HD*16; i += 512) S[i] = 0.f;
    __syncthreads();

    for (int c = 0; c < NC; ++c) {
        size_t tbase = ((size_t)c*CH*NH + h)*HD;
        for (int i = tid; i < CH*HD; i += 512) {
            int tt = i >> 7, kk = i & 127;
            size_t go = tbase + (size_t)tt*ROW + kk;
            KbS[tt*129+kk] = gg[go];
            QtS[tt*129+kk] = gq[go];
            KrS[tt*129+kk] = gk[go];
        }
        size_t mbase = (size_t)(c*NH + h) * CH * CH;
        for (int i = tid; i < 4096; i += 512) MS[(i>>6)*65 + (i&63)] = gM[mbase + i];
        for (int i = tid; i < 1024; i += 512) {
            int tt = i >> 4, j = i & 15;
            VbS[i] = gv[tbase + (size_t)tt*ROW + j0 + j];
        }
        if (tid < HD) cpS[tid] = gCp[(c*NH+h)*HD + tid];
        __syncthreads();

        // ---- Delta = Vb - Kb @ S ----
        float4 a4[4];
        if (kq == 0) {
            const float4* vr = (const float4*)(VbS + t*16);
#pragma unroll
            for (int q4 = 0; q4 < 4; ++q4) a4[q4] = vr[q4];
        } else {
#pragma unroll
            for (int q4 = 0; q4 < 4; ++q4) a4[q4] = make_float4(0.f,0.f,0.f,0.f);
        }
#pragma unroll
        for (int kk = 0; kk < 16; ++kk) {
            int k = k0 + kk;
            float kb = KbS[t*129 + k];
            const float4* sr = (const float4*)(S + k*16);
#pragma unroll
            for (int q4 = 0; q4 < 4; ++q4) {
                float4 sv = sr[q4];
                a4[q4].x -= kb*sv.x; a4[q4].y -= kb*sv.y;
                a4[q4].z -= kb*sv.z; a4[q4].w -= kb*sv.w;
            }
        }
        {
            float* af = (float*)a4;
#pragma unroll
            for (int m = 1; m < 8; m <<= 1)
#pragma unroll
                for (int j = 0; j < 16; ++j) af[j] += __shfl_xor_sync(~0u, af[j], m);
        }
        if (kq == 0) {
            float4* dr = (float4*)(DS + t*16);
#pragma unroll
            for (int q4 = 0; q4 < 4; ++q4) dr[q4] = a4[q4];
        }
        __syncthreads();

        // ---- O = Qt @ S + M @ Delta ----
#pragma unroll
        for (int q4 = 0; q4 < 4; ++q4) a4[q4] = make_float4(0.f,0.f,0.f,0.f);
#pragma unroll
        for (int kk = 0; kk < 16; ++kk) {
            int k = k0 + kk;
            float qv = QtS[t*129 + k];
            const float4* sr = (const float4*)(S + k*16);
#pragma unroll
            for (int q4 = 0; q4 < 4; ++q4) {
                float4 sv = sr[q4];
                a4[q4].x += qv*sv.x; a4[q4].y += qv*sv.y;
                a4[q4].z += qv*sv.z; a4[q4].w += qv*sv.w;
            }
        }
#pragma unroll
        for (int ss = 0; ss < 8; ++ss) {
            int s = kq*8 + ss;
            float mv = MS[t*65 + s];
            const float4* dr = (const float4*)(DS + s*16);
#pragma unroll
            for (int q4 = 0; q4 < 4; ++q4) {
                float4 dv = dr[q4];
                a4[q4].x += mv*dv.x; a4[q4].y += mv*dv.y;
                a4[q4].z += mv*dv.z; a4[q4].w += mv*dv.w;
            }
        }
        {
            float* af = (float*)a4;
#pragma unroll
            for (int m = 1; m < 8; m <<= 1)
#pragma unroll
                for (int j = 0; j < 16; ++j) af[j] += __shfl_xor_sync(~0u, af[j], m);
        }
        if (kq == 0) {
            float4* op = (float4*)(out + ((size_t)(c*CH + t)*NH + h)*HD + j0);
#pragma unroll
            for (int q4 = 0; q4 < 4; ++q4) op[q4] = a4[q4];
        }
        __syncthreads();

        // ---- S = cp .* S + Kbar^T @ Delta ----
        {
            float cp = cpS[krow];
            float4* srow = (float4*)(S + krow*16) + jq;
            float4 sa = *srow;
            sa.x *= cp; sa.y *= cp; sa.z *= cp; sa.w *= cp;
#pragma unroll 4
            for (int s = 0; s < CH; ++s) {
                float kb = KrS[s*129 + krow];
                float4 dv = *((const float4*)(DS + s*16) + jq);
                sa.x += kb*dv.x; sa.y += kb*dv.y;
                sa.z += kb*dv.z; sa.w += kb*dv.w;
            }
            *srow = sa;
        }
        __syncthreads();
    }
}

// =========================================================================
extern "C" void kernel_launch(void* const* d_in, const int* in_sizes, int n_in,
                              void* d_out, int out_size)
{
    (void)in_sizes; (void)n_in; (void)out_size;
    const float* qkv  = (const float*)d_in[0];
    const float* fg   = (const float*)d_in[1];
    const float* beta = (const float*)d_in[2];
    const float* cw   = (const float*)d_in[3];
    const float* dtb  = (const float*)d_in[4];
    const float* alog = (const float*)d_in[5];
    float* out = (float*)d_out;

    int smem2 = (3*64*129 + 64*64 + 64) * 4;                              // 115712
    int smem3 = (3*64*129 + 64*65 + 1024 + 1024 + 128 + 2048) * 4;        // 132608
    cudaFuncSetAttribute(k_phase2, cudaFuncAttributeMaxDynamicSharedMemorySize, smem2);
    cudaFuncSetAttribute(k_phase3, cudaFuncAttributeMaxDynamicSharedMemorySize, smem3);

    k_phase1<<<dim3(NC, NH), 128>>>(qkv, fg, beta, cw, dtb, alog);
    k_phase2<<<dim3(NC, NH), 256, smem2>>>();
    k_phase3<<<dim3(8, NH), 512, smem3>>>(out);
}

// round 7
// speedup vs baseline: 5.2718x; 5.2718x over previous
#include <cuda_runtime.h>
#include <math.h>

#define T_TOK 8192
#define NH 16
#define HD 128
#define CH 64
#define NC 128
#define ROW (NH*HD)   // 2048

// ------------------- device scratch (allocation-free) -------------------
__device__ float gq [T_TOK*ROW];   // q      -> q~ (phase2)
__device__ float gk [T_TOK*ROW];   // k      -> Kbar
__device__ float gv [T_TOK*ROW];   // v      -> Vb
__device__ float gg [T_TOK*ROW];   // g(log) -> Kb
__device__ float gb [T_TOK*NH];
__device__ float gM [NC*NH*CH*CH];
__device__ float gCp[NC*NH*HD];

// =========================================================================
// Phase 1: conv(K=4)+SiLU, l2norm q/k, gates.  grid (NC, NH), block 128
// Rolling 3-register window kills the 4x redundant conv re-reads.
// =========================================================================
__global__ void __launch_bounds__(128) k_phase1(
    const float* __restrict__ qkv, const float* __restrict__ fg,
    const float* __restrict__ beta, const float* __restrict__ cw,
    const float* __restrict__ dtb, const float* __restrict__ alog)
{
    int h = blockIdx.y, t0 = blockIdx.x * CH, d = threadIdx.x;
    int cq = h*HD + d, ck = ROW + cq, cv = 2*ROW + cq;
    float wq[4], wk[4], wv[4];
#pragma unroll
    for (int j = 0; j < 4; ++j) {
        wq[j] = cw[cq*4 + j];
        wk[j] = cw[ck*4 + j];
        wv[j] = cw[cv*4 + j];
    }
    float ea  = expf(alog[h]);
    float dtv = dtb[h*HD + d];
    __shared__ float red[8];
    int wid = d >> 5, lid = d & 31;

    // rolling window: p*[0]=x[t-3], p*[1]=x[t-2], p*[2]=x[t-1]
    float pq[3] = {0.f,0.f,0.f}, pk[3] = {0.f,0.f,0.f}, pv[3] = {0.f,0.f,0.f};
#pragma unroll
    for (int j = 0; j < 3; ++j) {
        int ts = t0 - 3 + j;
        if (ts >= 0) {
            const float* row = qkv + (size_t)ts * (3*ROW);
            pq[j] = row[cq]; pk[j] = row[ck]; pv[j] = row[cv];
        }
    }

    for (int tt = 0; tt < CH; ++tt) {
        int t = t0 + tt;
        const float* row = qkv + (size_t)t * (3*ROW);
        float rq = row[cq], rk = row[ck], rv = row[cv];
        float xq = pq[0]*wq[0] + pq[1]*wq[1] + pq[2]*wq[2] + rq*wq[3];
        float xk = pk[0]*wk[0] + pk[1]*wk[1] + pk[2]*wk[2] + rk*wk[3];
        float xv = pv[0]*wv[0] + pv[1]*wv[1] + pv[2]*wv[2] + rv*wv[3];
        pq[0]=pq[1]; pq[1]=pq[2]; pq[2]=rq;
        pk[0]=pk[1]; pk[1]=pk[2]; pk[2]=rk;
        pv[0]=pv[1]; pv[1]=pv[2]; pv[2]=rv;
        // SiLU
        xq = xq / (1.f + __expf(-xq));
        xk = xk / (1.f + __expf(-xk));
        xv = xv / (1.f + __expf(-xv));
        // block reduce q^2, k^2
        float sq = xq*xq, sk = xk*xk;
#pragma unroll
        for (int m = 16; m; m >>= 1) {
            sq += __shfl_xor_sync(~0u, sq, m);
            sk += __shfl_xor_sync(~0u, sk, m);
        }
        if (lid == 0) { red[wid] = sq; red[4+wid] = sk; }
        __syncthreads();
        float tq  = red[0]+red[1]+red[2]+red[3];
        float tk2 = red[4]+red[5]+red[6]+red[7];
        __syncthreads();
        float qn = xq * rsqrtf(tq  + 1e-6f) * 0.08838834764831845f; // D^-1/2
        float kn = xk * rsqrtf(tk2 + 1e-6f);
        // gate: g = -exp(alog)*softplus(fg + dt_bias)
        float gr = fg[(size_t)t*ROW + h*HD + d] + dtv;
        float sp = (gr > 20.f) ? gr : log1pf(__expf(gr));
        float gl = -ea * sp;
        size_t o = ((size_t)t*NH + h)*HD + d;
        gq[o] = qn; gk[o] = kn; gv[o] = xv; gg[o] = gl;
        if (d == 0) {
            float bb = beta[t*NH + h];
            gb[t*NH + h] = 1.f / (1.f + __expf(-bb));
        }
    }
}

// =========================================================================
// Phase 2: per (chunk, head) tile. gc cumsum, pair matrices A/M,
// forward substitution (I+L)^{-1} [b*v | b*k~] -> Vb, Kb.
// grid (NC, NH), block 256, dyn smem ~113 KB  (kept verbatim from R6)
// =========================================================================
__global__ void __launch_bounds__(256) k_phase2()
{
    extern __shared__ float sm[];
    float* gcS = sm;               // 64*129 (later ZB = Kb)
    float* qS  = gcS + 64*129;     // 64*129 (later ZA = Vb)
    float* kS  = qS  + 64*129;     // 64*129
    float* Ls  = kS  + 64*129;     // 64*64
    float* bS  = Ls  + 64*64;      // 64

    int c = blockIdx.x, h = blockIdx.y, tid = threadIdx.x;
    size_t tbase = ((size_t)c*CH*NH + h)*HD;

    for (int i = tid; i < CH*HD; i += 256) {
        int t = i >> 7, k = i & 127;
        size_t go = tbase + (size_t)t*ROW + k;
        gcS[t*129+k] = gg[go];
        qS [t*129+k] = gq[go];
        kS [t*129+k] = gk[go];
    }
    if (tid < CH) bS[tid] = gb[(c*CH + tid)*NH + h];
    __syncthreads();

    if (tid < HD) {
        float run = 0.f;
        for (int t = 0; t < CH; ++t) { run += gcS[t*129+tid]; gcS[t*129+tid] = run; }
    }
    __syncthreads();

    for (int i = tid; i < CH*HD; i += 256) {
        int t = i >> 7, k = i & 127;
        float gct = gcS[t*129+k];
        float g63 = gcS[63*129+k];
        size_t go = tbase + (size_t)t*ROW + k;
        gq[go] = qS[t*129+k] * __expf(gct);
        gk[go] = kS[t*129+k] * __expf(g63 - gct);
    }
    if (tid < HD) gCp[(c*NH+h)*HD + tid] = __expf(gcS[63*129+tid]);

    size_t mbase = (size_t)(c*NH + h) * CH * CH;
    for (int p = tid; p < 2080; p += 256) {
        int t = (int)((sqrtf(8.f*p + 1.f) - 1.f) * 0.5f);
        while ((t+1)*(t+2)/2 <= p) ++t;
        while (t*(t+1)/2 > p) --t;
        int s = p - t*(t+1)/2;
        const float* gt = gcS + t*129; const float* gs = gcS + s*129;
        const float* kt = kS  + t*129; const float* ksr = kS + s*129;
        const float* qt = qS  + t*129;
        float a = 0.f, m = 0.f;
#pragma unroll 4
        for (int k = 0; k < HD; ++k) {
            float e  = __expf(gt[k] - gs[k]);   // exponent <= 0 : safe
            float kv = ksr[k] * e;
            a += kt[k]*kv;
            m += qt[k]*kv;
        }
        gM[mbase + t*64 + s] = m;
        if (s < t) Ls[t*64 + s] = bS[t] * a;
    }
    for (int i = tid; i < 4096; i += 256) {
        int t = i >> 6, s = i & 63;
        if (s > t) gM[mbase + i] = 0.f;
    }
    __syncthreads();

    for (int i = tid; i < CH*HD; i += 256) {
        int t = i >> 7, k = i & 127;
        size_t go = tbase + (size_t)t*ROW + k;
        float bb = bS[t];
        qS [t*129+k] = bb * gv[go];
        gcS[t*129+k] = bb * kS[t*129+k] * __expf(gcS[t*129+k]);
    }
    __syncthreads();

    {
        float* Z = (tid < 128) ? qS : gcS;
        int col = tid & 127;
        for (int t = 1; t < CH; ++t) {
            float acc = 0.f;
            const float* lrow = Ls + t*64;
            for (int s = 0; s < t; ++s) acc += lrow[s] * Z[s*129 + col];
            Z[t*129 + col] -= acc;
        }
    }
    __syncthreads();

    for (int i = tid; i < CH*HD; i += 256) {
        int t = i >> 7, k = i & 127;
        size_t go = tbase + (size_t)t*ROW + k;
        gv[go] = qS [t*129+k];
        gg[go] = gcS[t*129+k];
    }
}

// =========================================================================
// Phase 3: sequential chunk scan, REDUCTION-FREE.
// grid (8, NH) = 128 blocks, 512 thr.
// Per chunk:  D = Vb - Kb@S ; O = Qt@S + M@D ; S = cp.*S + Kbar^T@D
// Thread maps: (t, jpair) for D/O ; (krow, jquad) for S-update.
// =========================================================================
#define ST3 132          // k-row stride (float4-aligned, bank-clean for our patterns)
#define MT3 68           // M row stride

__global__ void __launch_bounds__(512) k_phase3(float* __restrict__ out)
{
    extern __shared__ float sm[];
    float* KbS = sm;                 // 64*132
    float* QtS = KbS + CH*ST3;       // 64*132
    float* KrS = QtS + CH*ST3;       // 64*132
    float* MS  = KrS + CH*ST3;       // 64*68
    float* VbS = MS  + CH*MT3;       // 64*16
    float* DS  = VbS + CH*16;        // 64*16
    float* cpS = DS  + CH*16;        // 128
    float* S   = cpS + HD;           // 128*16

    int h = blockIdx.y, j0 = blockIdx.x * 16, tid = threadIdx.x;
    int t  = tid >> 3, jh = tid & 7;        // D/O mapping: j = jh*2
    int krow = tid >> 2, jq = tid & 3;      // S-update mapping

    for (int i = tid; i < HD*16; i += 512) S[i] = 0.f;
    __syncthreads();

    for (int c = 0; c < NC; ++c) {
        size_t tbase = ((size_t)c*CH*NH + h)*HD;
        // ---- stage (vectorized) ----
#pragma unroll
        for (int i = tid; i < CH*HD/4; i += 512) {      // 4 iters
            int tt = i >> 5, k4 = (i & 31) * 4;
            size_t go = tbase + (size_t)tt*ROW + k4;
            *(float4*)(KbS + tt*ST3 + k4) = *(const float4*)(gg + go);
            *(float4*)(QtS + tt*ST3 + k4) = *(const float4*)(gq + go);
            *(float4*)(KrS + tt*ST3 + k4) = *(const float4*)(gk + go);
        }
        {
            size_t mbase = (size_t)(c*NH + h) * CH * CH;
#pragma unroll
            for (int f = tid; f < 1024; f += 512) {     // 2 iters, float4
                int tt = f >> 4, s4 = (f & 15) * 4;
                *(float4*)(MS + tt*MT3 + s4) = *(const float4*)(gM + mbase + tt*64 + s4);
            }
        }
        if (tid < 256) {
            int tt = tid >> 2, j4 = (tid & 3) * 4;
            *(float4*)(VbS + tt*16 + j4) =
                *(const float4*)(gv + tbase + (size_t)tt*ROW + j0 + j4);
        }
        if (tid < HD) cpS[tid] = gCp[(c*NH+h)*HD + tid];
        __syncthreads();

        // ---- Delta = Vb - Kb @ S  (thread owns (t, j..j+1)) ----
        {
            const float* kbr = KbS + t*ST3;
            float2 a0 = *(const float2*)(VbS + t*16 + jh*2);
            float2 a1 = make_float2(0.f, 0.f);
#pragma unroll 8
            for (int k = 0; k < HD; k += 2) {
                float kb0 = kbr[k], kb1 = kbr[k+1];
                float2 s0 = *(const float2*)(S + k*16 + jh*2);
                float2 s1 = *(const float2*)(S + (k+1)*16 + jh*2);
                a0.x -= kb0*s0.x; a0.y -= kb0*s0.y;
                a1.x -= kb1*s1.x; a1.y -= kb1*s1.y;
            }
            a0.x += a1.x; a0.y += a1.y;
            *(float2*)(DS + t*16 + jh*2) = a0;
        }
        __syncthreads();

        // ---- O = Qt @ S + M @ Delta ----
        {
            const float* qtr = QtS + t*ST3;
            float2 o0 = make_float2(0.f, 0.f), o1 = make_float2(0.f, 0.f);
#pragma unroll 8
            for (int k = 0; k < HD; k += 2) {
                float q0 = qtr[k], q1 = qtr[k+1];
                float2 s0 = *(const float2*)(S + k*16 + jh*2);
                float2 s1 = *(const float2*)(S + (k+1)*16 + jh*2);
                o0.x += q0*s0.x; o0.y += q0*s0.y;
                o1.x += q1*s1.x; o1.y += q1*s1.y;
            }
            const float* mr = MS + t*MT3;
#pragma unroll 8
            for (int s = 0; s < CH; s += 2) {
                float m0 = mr[s], m1 = mr[s+1];
                float2 d0 = *(const float2*)(DS + s*16 + jh*2);
                float2 d1 = *(const float2*)(DS + (s+1)*16 + jh*2);
                o0.x += m0*d0.x; o0.y += m0*d0.y;
                o1.x += m1*d1.x; o1.y += m1*d1.y;
            }
            o0.x += o1.x; o0.y += o1.y;
            *(float2*)(out + ((size_t)(c*CH + t)*NH + h)*HD + j0 + jh*2) = o0;
        }
        __syncthreads();

        // ---- S = cp .* S + Kbar^T @ Delta  (thread owns (krow, jquad)) ----
        {
            float cp = cpS[krow];
            float4* sp4 = (float4*)(S + krow*16 + jq*4);
            float4 sa = *sp4;
            sa.x *= cp; sa.y *= cp; sa.z *= cp; sa.w *= cp;
#pragma unroll 8
            for (int s = 0; s < CH; ++s) {
                float kb = KrS[s*ST3 + krow];
                float4 dv = *(const float4*)(DS + s*16 + jq*4);
                sa.x += kb*dv.x; sa.y += kb*dv.y;
                sa.z += kb*dv.z; sa.w += kb*dv.w;
            }
            *sp4 = sa;
        }
        __syncthreads();
    }
}

// =========================================================================
extern "C" void kernel_launch(void* const* d_in, const int* in_sizes, int n_in,
                              void* d_out, int out_size)
{
    (void)in_sizes; (void)n_in; (void)out_size;
    const float* qkv  = (const float*)d_in[0];
    const float* fg   = (const float*)d_in[1];
    const float* beta = (const float*)d_in[2];
    const float* cw   = (const float*)d_in[3];
    const float* dtb  = (const float*)d_in[4];
    const float* alog = (const float*)d_in[5];
    float* out = (float*)d_out;

    int smem2 = (3*64*129 + 64*64 + 64) * 4;                               // 115,712
    int smem3 = (3*CH*ST3 + CH*MT3 + CH*16*2 + HD + HD*16) * 4;            // 134,912
    cudaFuncSetAttribute(k_phase2, cudaFuncAttributeMaxDynamicSharedMemorySize, smem2);
    cudaFuncSetAttribute(k_phase3, cudaFuncAttributeMaxDynamicSharedMemorySize, smem3);

    k_phase1<<<dim3(NC, NH), 128>>>(qkv, fg, beta, cw, dtb, alog);
    k_phase2<<<dim3(NC, NH), 256, smem2>>>();
    k_phase3<<<dim3(8, NH), 512, smem3>>>(out);
}

// round 8
// speedup vs baseline: 6.5316x; 1.2390x over previous
#include <cuda_runtime.h>
#include <math.h>

#define T_TOK 8192
#define NH 16
#define HD 128
#define CH 64
#define NC 128
#define ROW (NH*HD)   // 2048

// ------------------- device scratch (allocation-free) -------------------
__device__ float gq [T_TOK*ROW];   // q      -> q~ (phase2)
__device__ float gk [T_TOK*ROW];   // k      -> Kbar
__device__ float gv [T_TOK*ROW];   // v      -> Vb
__device__ float gg [T_TOK*ROW];   // g(log) -> Kb
__device__ float gb [T_TOK*NH];
__device__ float gM [NC*NH*CH*CH];
__device__ float gCp[NC*NH*HD];

// =========================================================================
// Phase 1: conv(K=4)+SiLU, l2norm q/k, gates.
// One warp per head (lane holds 4 dims, float4 I/O), 4 heads per block.
// grid (NC, 4), block 128.
// =========================================================================
__global__ void __launch_bounds__(128) k_phase1(
    const float* __restrict__ qkv, const float* __restrict__ fg,
    const float* __restrict__ beta, const float* __restrict__ cw,
    const float* __restrict__ dtb, const float* __restrict__ alog)
{
    int w = threadIdx.x >> 5, l = threadIdx.x & 31;
    int h = blockIdx.y * 4 + w;
    int t0 = blockIdx.x * CH;
    int d0 = l * 4;
    int cq = h*HD + d0, ck = ROW + cq, cv = 2*ROW + cq;

    float wq[4][4], wk[4][4], wv[4][4];   // [elem][tap]
#pragma unroll
    for (int e = 0; e < 4; ++e)
#pragma unroll
        for (int j = 0; j < 4; ++j) {
            wq[e][j] = cw[(cq+e)*4 + j];
            wk[e][j] = cw[(ck+e)*4 + j];
            wv[e][j] = cw[(cv+e)*4 + j];
        }
    float ea = expf(alog[h]);
    float dtv[4];
    *(float4*)dtv = *(const float4*)(dtb + h*HD + d0);

    // rolling window x[t-3..t-1]
    float pq[3][4], pk[3][4], pv[3][4];
#pragma unroll
    for (int j = 0; j < 3; ++j) {
        int ts = t0 - 3 + j;
        if (ts >= 0) {
            const float* row = qkv + (size_t)ts * (3*ROW);
            *(float4*)pq[j] = *(const float4*)(row + cq);
            *(float4*)pk[j] = *(const float4*)(row + ck);
            *(float4*)pv[j] = *(const float4*)(row + cv);
        } else {
#pragma unroll
            for (int e = 0; e < 4; ++e) { pq[j][e]=0.f; pk[j][e]=0.f; pv[j][e]=0.f; }
        }
    }

    for (int tt = 0; tt < CH; ++tt) {
        int t = t0 + tt;
        const float* row = qkv + (size_t)t * (3*ROW);
        float rq[4], rk[4], rv[4];
        *(float4*)rq = *(const float4*)(row + cq);
        *(float4*)rk = *(const float4*)(row + ck);
        *(float4*)rv = *(const float4*)(row + cv);
        float fgv[4];
        *(float4*)fgv = *(const float4*)(fg + (size_t)t*ROW + h*HD + d0);

        float xq[4], xk[4], xv[4];
#pragma unroll
        for (int e = 0; e < 4; ++e) {
            float aq = pq[0][e]*wq[e][0] + pq[1][e]*wq[e][1] + pq[2][e]*wq[e][2] + rq[e]*wq[e][3];
            float ak = pk[0][e]*wk[e][0] + pk[1][e]*wk[e][1] + pk[2][e]*wk[e][2] + rk[e]*wk[e][3];
            float av = pv[0][e]*wv[e][0] + pv[1][e]*wv[e][1] + pv[2][e]*wv[e][2] + rv[e]*wv[e][3];
            xq[e] = aq / (1.f + __expf(-aq));
            xk[e] = ak / (1.f + __expf(-ak));
            xv[e] = av / (1.f + __expf(-av));
        }
#pragma unroll
        for (int j = 0; j < 2; ++j)
#pragma unroll
            for (int e = 0; e < 4; ++e) { pq[j][e]=pq[j+1][e]; pk[j][e]=pk[j+1][e]; pv[j][e]=pv[j+1][e]; }
#pragma unroll
        for (int e = 0; e < 4; ++e) { pq[2][e]=rq[e]; pk[2][e]=rk[e]; pv[2][e]=rv[e]; }

        float sq = xq[0]*xq[0]+xq[1]*xq[1]+xq[2]*xq[2]+xq[3]*xq[3];
        float sk = xk[0]*xk[0]+xk[1]*xk[1]+xk[2]*xk[2]+xk[3]*xk[3];
#pragma unroll
        for (int m = 16; m; m >>= 1) {
            sq += __shfl_xor_sync(~0u, sq, m);
            sk += __shfl_xor_sync(~0u, sk, m);
        }
        float rnq = rsqrtf(sq + 1e-6f) * 0.08838834764831845f; // * D^-1/2
        float rnk = rsqrtf(sk + 1e-6f);

        float oq[4], ok[4], og[4];
#pragma unroll
        for (int e = 0; e < 4; ++e) {
            oq[e] = xq[e] * rnq;
            ok[e] = xk[e] * rnk;
            float gr = fgv[e] + dtv[e];
            float sp = (gr > 20.f) ? gr : log1pf(__expf(gr));
            og[e] = -ea * sp;
        }
        size_t o = ((size_t)t*NH + h)*HD + d0;
        *(float4*)(gq + o) = *(float4*)oq;
        *(float4*)(gk + o) = *(float4*)ok;
        *(float4*)(gv + o) = *(float4*)xv;
        *(float4*)(gg + o) = *(float4*)og;
        if (l == 0) {
            float bb = beta[t*NH + h];
            gb[t*NH + h] = 1.f / (1.f + __expf(-bb));
        }
    }
}

// =========================================================================
// Phase 2: per (chunk, head) tile. gc cumsum, pair matrices A/M,
// forward substitution (I+L)^{-1} [b*v | b*k~] -> Vb, Kb.
// grid (NC, NH), block 512, dyn smem ~113 KB
// =========================================================================
__global__ void __launch_bounds__(512) k_phase2()
{
    extern __shared__ float sm[];
    float* gcS = sm;               // 64*129 (later ZB = Kb)
    float* qS  = gcS + 64*129;     // 64*129 (later ZA = Vb)
    float* kS  = qS  + 64*129;     // 64*129
    float* Ls  = kS  + 64*129;     // 64*64
    float* bS  = Ls  + 64*64;      // 64

    int c = blockIdx.x, h = blockIdx.y, tid = threadIdx.x;
    size_t tbase = ((size_t)c*CH*NH + h)*HD;

    for (int i = tid; i < CH*HD; i += 512) {
        int t = i >> 7, k = i & 127;
        size_t go = tbase + (size_t)t*ROW + k;
        gcS[t*129+k] = gg[go];
        qS [t*129+k] = gq[go];
        kS [t*129+k] = gk[go];
    }
    if (tid < CH) bS[tid] = gb[(c*CH + tid)*NH + h];
    __syncthreads();

    if (tid < HD) {
        float run = 0.f;
        for (int t = 0; t < CH; ++t) { run += gcS[t*129+tid]; gcS[t*129+tid] = run; }
    }
    __syncthreads();

    for (int i = tid; i < CH*HD; i += 512) {
        int t = i >> 7, k = i & 127;
        float gct = gcS[t*129+k];
        float g63 = gcS[63*129+k];
        size_t go = tbase + (size_t)t*ROW + k;
        gq[go] = qS[t*129+k] * __expf(gct);
        gk[go] = kS[t*129+k] * __expf(g63 - gct);
    }
    if (tid < HD) gCp[(c*NH+h)*HD + tid] = __expf(gcS[63*129+tid]);

    size_t mbase = (size_t)(c*NH + h) * CH * CH;
    for (int p = tid; p < 2080; p += 512) {
        int t = (int)((sqrtf(8.f*p + 1.f) - 1.f) * 0.5f);
        while ((t+1)*(t+2)/2 <= p) ++t;
        while (t*(t+1)/2 > p) --t;
        int s = p - t*(t+1)/2;
        const float* gt = gcS + t*129; const float* gs = gcS + s*129;
        const float* kt = kS  + t*129; const float* ksr = kS + s*129;
        const float* qt = qS  + t*129;
        float a = 0.f, m = 0.f;
#pragma unroll 4
        for (int k = 0; k < HD; ++k) {
            float e  = __expf(gt[k] - gs[k]);   // exponent <= 0 : safe
            float kv = ksr[k] * e;
            a += kt[k]*kv;
            m += qt[k]*kv;
        }
        gM[mbase + t*64 + s] = m;
        if (s < t) Ls[t*64 + s] = bS[t] * a;
    }
    for (int i = tid; i < 4096; i += 512) {
        int t = i >> 6, s = i & 63;
        if (s > t) gM[mbase + i] = 0.f;
    }
    __syncthreads();

    for (int i = tid; i < CH*HD; i += 512) {
        int t = i >> 7, k = i & 127;
        size_t go = tbase + (size_t)t*ROW + k;
        float bb = bS[t];
        qS [t*129+k] = bb * gv[go];
        gcS[t*129+k] = bb * kS[t*129+k] * __expf(gcS[t*129+k]);
    }
    __syncthreads();

    if (tid < 256) {
        float* Z = (tid < 128) ? qS : gcS;
        int col = tid & 127;
        for (int t = 1; t < CH; ++t) {
            float acc = 0.f;
            const float* lrow = Ls + t*64;
            for (int s = 0; s < t; ++s) acc += lrow[s] * Z[s*129 + col];
            Z[t*129 + col] -= acc;
        }
    }
    __syncthreads();

    for (int i = tid; i < CH*HD; i += 512) {
        int t = i >> 7, k = i & 127;
        size_t go = tbase + (size_t)t*ROW + k;
        gv[go] = qS [t*129+k];
        gg[go] = gcS[t*129+k];
    }
}

// =========================================================================
// Phase 3: sequential chunk scan, fused Qt@S into Delta pass, register-
// prefetched staging of the next chunk. grid (8, NH), block 512.
// Per chunk: [D = Vb - Kb@S ; X = Qt@S] ; O = X + M@D ; S = cp.*S + Kbar^T@D
// =========================================================================
#define ST3 132          // k-row stride (float4-aligned)
#define MT3 68           // M row stride

__global__ void __launch_bounds__(512) k_phase3(float* __restrict__ out)
{
    extern __shared__ float sm[];
    float* KbS = sm;                 // 64*132
    float* QtS = KbS + CH*ST3;
    float* KrS = QtS + CH*ST3;
    float* MS  = KrS + CH*ST3;       // 64*68
    float* VbS = MS  + CH*MT3;       // 64*16
    float* DS  = VbS + CH*16;        // 64*16
    float* cpS = DS  + CH*16;        // 128
    float* S   = cpS + HD;           // 128*16

    int h = blockIdx.y, j0 = blockIdx.x * 16, tid = threadIdx.x;
    int t  = tid >> 3, jh = tid & 7;        // D/O mapping: j = jh*2
    int krow = tid >> 2, jq = tid & 3;      // S-update mapping

    // prefetch registers for the big tiles (Kb, Qt, Kr)
    float4 rKb[4], rQt[4], rQr[4];

    // precomputed per-thread staging coords
    int stt[4], sk4[4];
#pragma unroll
    for (int i = 0; i < 4; ++i) {
        int idx = tid + i*512;
        stt[i] = idx >> 5; sk4[i] = (idx & 31) * 4;
    }

    for (int i = tid; i < HD*16; i += 512) S[i] = 0.f;

    // ---- prologue: load + store chunk 0 ----
    {
        size_t tbase = ((size_t)h)*HD;  // c=0
#pragma unroll
        for (int i = 0; i < 4; ++i) {
            size_t go = tbase + (size_t)stt[i]*ROW + sk4[i];
            rKb[i] = *(const float4*)(gg + go);
            rQt[i] = *(const float4*)(gq + go);
            rQr[i] = *(const float4*)(gk + go);
        }
#pragma unroll
        for (int i = 0; i < 4; ++i) {
            *(float4*)(KbS + stt[i]*ST3 + sk4[i]) = rKb[i];
            *(float4*)(QtS + stt[i]*ST3 + sk4[i]) = rQt[i];
            *(float4*)(KrS + stt[i]*ST3 + sk4[i]) = rQr[i];
        }
#pragma unroll
        for (int f = tid; f < 1024; f += 512) {
            int tt = f >> 4, s4 = (f & 15) * 4;
            *(float4*)(MS + tt*MT3 + s4) = *(const float4*)(gM + (size_t)h*CH*CH + tt*64 + s4);
        }
        if (tid < 256) {
            int tt = tid >> 2, j4 = (tid & 3) * 4;
            *(float4*)(VbS + tt*16 + j4) = *(const float4*)(gv + tbase + (size_t)tt*ROW + j0 + j4);
        }
        if (tid < HD) cpS[tid] = gCp[h*HD + tid];
    }
    __syncthreads();

    for (int c = 0; c < NC; ++c) {
        // ---- issue prefetch for chunk c+1 ----
        if (c + 1 < NC) {
            size_t tbase1 = ((size_t)(c+1)*CH*NH + h)*HD;
#pragma unroll
            for (int i = 0; i < 4; ++i) {
                size_t go = tbase1 + (size_t)stt[i]*ROW + sk4[i];
                rKb[i] = *(const float4*)(gg + go);
                rQt[i] = *(const float4*)(gq + go);
                rQr[i] = *(const float4*)(gk + go);
            }
        }

        // ---- D = Vb - Kb@S  and  X = Qt@S (fused, shared S loads) ----
        float2 a0, x0, x1;
        {
            const float* kbr = KbS + t*ST3;
            const float* qtr = QtS + t*ST3;
            a0 = *(const float2*)(VbS + t*16 + jh*2);
            float2 a1 = make_float2(0.f, 0.f);
            x0 = make_float2(0.f, 0.f); x1 = make_float2(0.f, 0.f);
#pragma unroll 8
            for (int k = 0; k < HD; k += 2) {
                float kb0 = kbr[k], kb1 = kbr[k+1];
                float q0 = qtr[k], q1 = qtr[k+1];
                float2 s0 = *(const float2*)(S + k*16 + jh*2);
                float2 s1 = *(const float2*)(S + (k+1)*16 + jh*2);
                a0.x -= kb0*s0.x; a0.y -= kb0*s0.y;
                a1.x -= kb1*s1.x; a1.y -= kb1*s1.y;
                x0.x += q0*s0.x;  x0.y += q0*s0.y;
                x1.x += q1*s1.x;  x1.y += q1*s1.y;
            }
            a0.x += a1.x; a0.y += a1.y;
            x0.x += x1.x; x0.y += x1.y;
            *(float2*)(DS + t*16 + jh*2) = a0;
        }
        __syncthreads();

        // ---- O = X + M@D  (no sync needed vs S-update: O no longer reads S) ----
        {
            float2 o0 = x0, o1 = make_float2(0.f, 0.f);
            const float* mr = MS + t*MT3;
#pragma unroll 8
            for (int s = 0; s < CH; s += 2) {
                float m0 = mr[s], m1 = mr[s+1];
                float2 d0 = *(const float2*)(DS + s*16 + jh*2);
                float2 d1 = *(const float2*)(DS + (s+1)*16 + jh*2);
                o0.x += m0*d0.x; o0.y += m0*d0.y;
                o1.x += m1*d1.x; o1.y += m1*d1.y;
            }
            o0.x += o1.x; o0.y += o1.y;
            *(float2*)(out + ((size_t)(c*CH + t)*NH + h)*HD + j0 + jh*2) = o0;
        }

        // ---- S = cp.*S + Kbar^T@D ----
        {
            float cp = cpS[krow];
            float4* sp4 = (float4*)(S + krow*16 + jq*4);
            float4 sa = *sp4;
            sa.x *= cp; sa.y *= cp; sa.z *= cp; sa.w *= cp;
#pragma unroll 8
            for (int s = 0; s < CH; ++s) {
                float kb = KrS[s*ST3 + krow];
                float4 dv = *(const float4*)(DS + s*16 + jq*4);
                sa.x += kb*dv.x; sa.y += kb*dv.y;
                sa.z += kb*dv.z; sa.w += kb*dv.w;
            }
            *sp4 = sa;
        }
        __syncthreads();

        // ---- store prefetched chunk c+1 into smem + small tiles ----
        if (c + 1 < NC) {
            size_t tbase1 = ((size_t)(c+1)*CH*NH + h)*HD;
#pragma unroll
            for (int i = 0; i < 4; ++i) {
                *(float4*)(KbS + stt[i]*ST3 + sk4[i]) = rKb[i];
                *(float4*)(QtS + stt[i]*ST3 + sk4[i]) = rQt[i];
                *(float4*)(KrS + stt[i]*ST3 + sk4[i]) = rQr[i];
            }
            size_t mbase1 = (size_t)((c+1)*NH + h) * CH * CH;
#pragma unroll
            for (int f = tid; f < 1024; f += 512) {
                int tt = f >> 4, s4 = (f & 15) * 4;
                *(float4*)(MS + tt*MT3 + s4) = *(const float4*)(gM + mbase1 + tt*64 + s4);
            }
            if (tid < 256) {
                int tt = tid >> 2, j4 = (tid & 3) * 4;
                *(float4*)(VbS + tt*16 + j4) =
                    *(const float4*)(gv + tbase1 + (size_t)tt*ROW + j0 + j4);
            }
            if (tid < HD) cpS[tid] = gCp[((c+1)*NH+h)*HD + tid];
            __syncthreads();
        }
    }
}

// =========================================================================
extern "C" void kernel_launch(void* const* d_in, const int* in_sizes, int n_in,
                              void* d_out, int out_size)
{
    (void)in_sizes; (void)n_in; (void)out_size;
    const float* qkv  = (const float*)d_in[0];
    const float* fg   = (const float*)d_in[1];
    const float* beta = (const float*)d_in[2];
    const float* cw   = (const float*)d_in[3];
    const float* dtb  = (const float*)d_in[4];
    const float* alog = (const float*)d_in[5];
    float* out = (float*)d_out;

    int smem2 = (3*64*129 + 64*64 + 64) * 4;                               // 115,712
    int smem3 = (3*CH*ST3 + CH*MT3 + CH*16*2 + HD + HD*16) * 4;            // 134,912
    cudaFuncSetAttribute(k_phase2, cudaFuncAttributeMaxDynamicSharedMemorySize, smem2);
    cudaFuncSetAttribute(k_phase3, cudaFuncAttributeMaxDynamicSharedMemorySize, smem3);

    k_phase1<<<dim3(NC, 4), 128>>>(qkv, fg, beta, cw, dtb, alog);
    k_phase2<<<dim3(NC, NH), 512, smem2>>>();
    k_phase3<<<dim3(8, NH), 512, smem3>>>(out);
}

// round 10
// speedup vs baseline: 6.5695x; 1.0058x over previous
#include <cuda_runtime.h>
#include <math.h>

#define T_TOK 8192
#define NH 16
#define HD 128
#define CH 64
#define NC 128
#define ROW (NH*HD)   // 2048

// ------------------- device scratch (allocation-free) -------------------
__device__ float gq [T_TOK*ROW];   // q      -> q~ (phase2)
__device__ float gk [T_TOK*ROW];   // k      -> Kbar
__device__ float gv [T_TOK*ROW];   // v      -> Vb
__device__ float gg [T_TOK*ROW];   // g(log) -> Kb
__device__ float gb [T_TOK*NH];
__device__ float gM [NC*NH*CH*CH];
__device__ float gCp[NC*NH*HD];

// =========================================================================
// Phase 1: conv(K=4)+SiLU, l2norm q/k, gates.
// Warp = one 16-token strip of one head (conv window is 3 deep -> strips
// independent). grid (NC, NH), block 128 (4 warps = 4 strips).
// =========================================================================
__global__ void __launch_bounds__(128) k_phase1(
    const float* __restrict__ qkv, const float* __restrict__ fg,
    const float* __restrict__ beta, const float* __restrict__ cw,
    const float* __restrict__ dtb, const float* __restrict__ alog)
{
    int w = threadIdx.x >> 5, l = threadIdx.x & 31;
    int h = blockIdx.y;
    int t0 = blockIdx.x * CH + w * 16;
    int d0 = l * 4;
    int cq = h*HD + d0, ck = ROW + cq, cv = 2*ROW + cq;

    float wq[4][4], wk[4][4], wv[4][4];   // [elem][tap]
#pragma unroll
    for (int e = 0; e < 4; ++e)
#pragma unroll
        for (int j = 0; j < 4; ++j) {
            wq[e][j] = cw[(cq+e)*4 + j];
            wk[e][j] = cw[(ck+e)*4 + j];
            wv[e][j] = cw[(cv+e)*4 + j];
        }
    float ea = expf(alog[h]);
    float dtv[4];
    *(float4*)dtv = *(const float4*)(dtb + h*HD + d0);

    // rolling window x[t0-3..t0-1]
    float pq[3][4], pk[3][4], pv[3][4];
#pragma unroll
    for (int j = 0; j < 3; ++j) {
        int ts = t0 - 3 + j;
        if (ts >= 0) {
            const float* row = qkv + (size_t)ts * (3*ROW);
            *(float4*)pq[j] = *(const float4*)(row + cq);
            *(float4*)pk[j] = *(const float4*)(row + ck);
            *(float4*)pv[j] = *(const float4*)(row + cv);
        } else {
#pragma unroll
            for (int e = 0; e < 4; ++e) { pq[j][e]=0.f; pk[j][e]=0.f; pv[j][e]=0.f; }
        }
    }

    for (int tt = 0; tt < 16; ++tt) {
        int t = t0 + tt;
        const float* row = qkv + (size_t)t * (3*ROW);
        float rq[4], rk[4], rv[4];
        *(float4*)rq = *(const float4*)(row + cq);
        *(float4*)rk = *(const float4*)(row + ck);
        *(float4*)rv = *(const float4*)(row + cv);
        float fgv[4];
        *(float4*)fgv = *(const float4*)(fg + (size_t)t*ROW + h*HD + d0);

        float xq[4], xk[4], xv[4];
#pragma unroll
        for (int e = 0; e < 4; ++e) {
            float aq = pq[0][e]*wq[e][0] + pq[1][e]*wq[e][1] + pq[2][e]*wq[e][2] + rq[e]*wq[e][3];
            float ak = pk[0][e]*wk[e][0] + pk[1][e]*wk[e][1] + pk[2][e]*wk[e][2] + rk[e]*wk[e][3];
            float av = pv[0][e]*wv[e][0] + pv[1][e]*wv[e][1] + pv[2][e]*wv[e][2] + rv[e]*wv[e][3];
            xq[e] = aq / (1.f + __expf(-aq));
            xk[e] = ak / (1.f + __expf(-ak));
            xv[e] = av / (1.f + __expf(-av));
        }
#pragma unroll
        for (int j = 0; j < 2; ++j)
#pragma unroll
            for (int e = 0; e < 4; ++e) { pq[j][e]=pq[j+1][e]; pk[j][e]=pk[j+1][e]; pv[j][e]=pv[j+1][e]; }
#pragma unroll
        for (int e = 0; e < 4; ++e) { pq[2][e]=rq[e]; pk[2][e]=rk[e]; pv[2][e]=rv[e]; }

        float sq = xq[0]*xq[0]+xq[1]*xq[1]+xq[2]*xq[2]+xq[3]*xq[3];
        float sk = xk[0]*xk[0]+xk[1]*xk[1]+xk[2]*xk[2]+xk[3]*xk[3];
#pragma unroll
        for (int m = 16; m; m >>= 1) {
            sq += __shfl_xor_sync(~0u, sq, m);
            sk += __shfl_xor_sync(~0u, sk, m);
        }
        float rnq = rsqrtf(sq + 1e-6f) * 0.08838834764831845f; // * D^-1/2
        float rnk = rsqrtf(sk + 1e-6f);

        float oq[4], ok[4], og[4];
#pragma unroll
        for (int e = 0; e < 4; ++e) {
            oq[e] = xq[e] * rnq;
            ok[e] = xk[e] * rnk;
            float gr = fgv[e] + dtv[e];
            float sp = (gr > 20.f) ? gr : log1pf(__expf(gr));
            og[e] = -ea * sp;
        }
        size_t o = ((size_t)t*NH + h)*HD + d0;
        *(float4*)(gq + o) = *(float4*)oq;
        *(float4*)(gk + o) = *(float4*)ok;
        *(float4*)(gv + o) = *(float4*)xv;
        *(float4*)(gg + o) = *(float4*)og;
        if (l == 0) {
            float bb = beta[t*NH + h];
            gb[t*NH + h] = 1.f / (1.f + __expf(-bb));
        }
    }
}

// =========================================================================
// Phase 2: per (chunk, head) tile.
// Pair matrices via 8t x 4s warp tiles with float4 k-chunks (no reductions,
// broadcast-dedup smem loads). Blocked forward substitution (4 x 16):
// small triangular solve + GEMM rank-updates.
// grid (NC, NH), block 512, dyn smem ~116 KB
// =========================================================================
#define P2S 132   // padded row stride (float4-aligned)

__global__ void __launch_bounds__(512) k_phase2()
{
    extern __shared__ float sm[];
    float* gcS = sm;               // 64*132 (later ZB = Kb)
    float* qS  = gcS + CH*P2S;     // 64*132 (later ZA = Vb)
    float* kS  = qS  + CH*P2S;     // 64*132
    float* Ls  = kS  + CH*P2S;     // 64*65
    float* bS  = Ls  + CH*65;      // 64

    int c = blockIdx.x, h = blockIdx.y, tid = threadIdx.x;
    size_t tbase = ((size_t)c*CH*NH + h)*HD;

    // ---- stage (float4) ----
#pragma unroll
    for (int i = tid; i < CH*HD/4; i += 512) {
        int t = i >> 5, k4 = (i & 31) * 4;
        size_t go = tbase + (size_t)t*ROW + k4;
        *(float4*)(gcS + t*P2S + k4) = *(const float4*)(gg + go);
        *(float4*)(qS  + t*P2S + k4) = *(const float4*)(gq + go);
        *(float4*)(kS  + t*P2S + k4) = *(const float4*)(gk + go);
    }
    if (tid < CH) bS[tid] = gb[(c*CH + tid)*NH + h];
    __syncthreads();

    // ---- gc cumsum over t ----
    if (tid < HD) {
        float run = 0.f;
        for (int t = 0; t < CH; ++t) { run += gcS[t*P2S+tid]; gcS[t*P2S+tid] = run; }
    }
    __syncthreads();

    // ---- q~ = q*exp(gc), Kbar = k*exp(gc63-gc), cp = exp(gc63) ----
    for (int i = tid; i < CH*HD; i += 512) {
        int t = i >> 7, k = i & 127;
        float gct = gcS[t*P2S+k];
        float g63 = gcS[63*P2S+k];
        size_t go = tbase + (size_t)t*ROW + k;
        gq[go] = qS[t*P2S+k] * __expf(gct);
        gk[go] = kS[t*P2S+k] * __expf(g63 - gct);
    }
    if (tid < HD) gCp[(c*NH+h)*HD + tid] = __expf(gcS[63*P2S+tid]);

    // ---- pair tiles: warp processes an 8t x 4s tile, lane=(tr,sc) ----
    size_t mbase = (size_t)(c*NH + h) * CH * CH;
    {
        int w = tid >> 5, l = tid & 31, tr = l >> 2, sc = l & 3;
        for (int tile = w; tile < 72; tile += 16) {
            int i = 0;
            while ((i+1)*(i+2) <= tile) ++i;    // tiles before row i = i*i+i
            int j = tile - i*(i+1);             // j in 0..2i+1
            int t = i*8 + tr, s = j*4 + sc;
            const float* gtr = gcS + t*P2S; const float* gsr = gcS + s*P2S;
            const float* ktr = kS  + t*P2S; const float* ksr = kS  + s*P2S;
            const float* qtr = qS  + t*P2S;
            float a = 0.f, m = 0.f;
#pragma unroll 4
            for (int k = 0; k < HD; k += 4) {
                float4 g1 = *(const float4*)(gtr + k);
                float4 g0 = *(const float4*)(gsr + k);
                float4 kt4 = *(const float4*)(ktr + k);
                float4 ks4 = *(const float4*)(ksr + k);
                float4 qt4 = *(const float4*)(qtr + k);
                float e, kv;
                e = __expf(g1.x - g0.x); kv = ks4.x * e; a += kt4.x*kv; m += qt4.x*kv;
                e = __expf(g1.y - g0.y); kv = ks4.y * e; a += kt4.y*kv; m += qt4.y*kv;
                e = __expf(g1.z - g0.z); kv = ks4.z * e; a += kt4.z*kv; m += qt4.z*kv;
                e = __expf(g1.w - g0.w); kv = ks4.w * e; a += kt4.w*kv; m += qt4.w*kv;
            }
            if (s <= t) gM[mbase + t*64 + s] = m;
            if (s <  t) Ls[t*65 + s] = bS[t] * a;
        }
    }
    // zero upper triangle of M
    for (int i = tid; i < 4096; i += 512) {
        int t = i >> 6, s = i & 63;
        if (s > t) gM[mbase + i] = 0.f;
    }
    __syncthreads();

    // ---- RHS in place: ZA(qS) = b*v, ZB(gcS) = b*k*exp(gc) ----
    for (int i = tid; i < CH*HD; i += 512) {
        int t = i >> 7, k = i & 127;
        size_t go = tbase + (size_t)t*ROW + k;
        float bb = bS[t];
        float zb = bb * kS[t*P2S+k] * __expf(gcS[t*P2S+k]);
        qS [t*P2S+k] = bb * gv[go];
        gcS[t*P2S+k] = zb;
    }
    __syncthreads();

    // ---- blocked forward substitution (I+L) Z = RHS ----
#pragma unroll
    for (int ib = 0; ib < 4; ++ib) {
        int i0 = ib * 16;
        // triangular solve within block: 256 column-threads
        if (tid < 256) {
            float* Z = (tid < 128) ? (qS + tid) : (gcS + (tid - 128));
            for (int t = i0+1; t < i0+16; ++t) {
                float acc = 0.f;
                const float* lrow = Ls + t*65;
                for (int s = i0; s < t; ++s) acc += lrow[s] * Z[s*P2S];
                Z[t*P2S] -= acc;
            }
        }
        __syncthreads();
        // GEMM rank-16 update of rows below
        int rows = 48 - 16*ib;
        if (rows > 0) {
            int slots = rows * 128;   // float2 per slot over 256 columns
            for (int sl = tid; sl < slots; sl += 512) {
                int t  = i0 + 16 + (sl >> 7);
                int c2 = sl & 127;
                float* Z = (c2 < 64) ? (qS + c2*2) : (gcS + (c2-64)*2);
                float2 acc = make_float2(0.f, 0.f);
                const float* lrow = Ls + t*65 + i0;
#pragma unroll
                for (int s = 0; s < 16; ++s) {
                    float lv = lrow[s];
                    float2 zv = *(const float2*)(Z + (i0+s)*P2S);
                    acc.x += lv*zv.x; acc.y += lv*zv.y;
                }
                float2 zt = *(float2*)(Z + t*P2S);
                zt.x -= acc.x; zt.y -= acc.y;
                *(float2*)(Z + t*P2S) = zt;
            }
        }
        __syncthreads();
    }

    // ---- write out: Vb -> gv, Kb -> gg ----
    for (int i = tid; i < CH*HD; i += 512) {
        int t = i >> 7, k = i & 127;
        size_t go = tbase + (size_t)t*ROW + k;
        gv[go] = qS [t*P2S+k];
        gg[go] = gcS[t*P2S+k];
    }
}

// =========================================================================
// Phase 3: sequential chunk scan, fused Qt@S into Delta pass, register-
// prefetched staging of the next chunk. grid (8, NH), block 512.
// Per chunk: [D = Vb - Kb@S ; X = Qt@S] ; O = X + M@D ; S = cp.*S + Kbar^T@D
// =========================================================================
#define ST3 132          // k-row stride (float4-aligned)
#define MT3 68           // M row stride

__global__ void __launch_bounds__(512) k_phase3(float* __restrict__ out)
{
    extern __shared__ float sm[];
    float* KbS = sm;                 // 64*132
    float* QtS = KbS + CH*ST3;
    float* KrS = QtS + CH*ST3;
    float* MS  = KrS + CH*ST3;       // 64*68
    float* VbS = MS  + CH*MT3;       // 64*16
    float* DS  = VbS + CH*16;        // 64*16
    float* cpS = DS  + CH*16;        // 128
    float* S   = cpS + HD;           // 128*16

    int h = blockIdx.y, j0 = blockIdx.x * 16, tid = threadIdx.x;
    int t  = tid >> 3, jh = tid & 7;        // D/O mapping: j = jh*2
    int krow = tid >> 2, jq = tid & 3;      // S-update mapping

    float4 rKb[4], rQt[4], rQr[4];
    int stt[4], sk4[4];
#pragma unroll
    for (int i = 0; i < 4; ++i) {
        int idx = tid + i*512;
        stt[i] = idx >> 5; sk4[i] = (idx & 31) * 4;
    }

    for (int i = tid; i < HD*16; i += 512) S[i] = 0.f;

    // ---- prologue: load + store chunk 0 ----
    {
        size_t tbase = ((size_t)h)*HD;
#pragma unroll
        for (int i = 0; i < 4; ++i) {
            size_t go = tbase + (size_t)stt[i]*ROW + sk4[i];
            rKb[i] = *(const float4*)(gg + go);
            rQt[i] = *(const float4*)(gq + go);
            rQr[i] = *(const float4*)(gk + go);
        }
#pragma unroll
        for (int i = 0; i < 4; ++i) {
            *(float4*)(KbS + stt[i]*ST3 + sk4[i]) = rKb[i];
            *(float4*)(QtS + stt[i]*ST3 + sk4[i]) = rQt[i];
            *(float4*)(KrS + stt[i]*ST3 + sk4[i]) = rQr[i];
        }
#pragma unroll
        for (int f = tid; f < 1024; f += 512) {
            int tt = f >> 4, s4 = (f & 15) * 4;
            *(float4*)(MS + tt*MT3 + s4) = *(const float4*)(gM + (size_t)h*CH*CH + tt*64 + s4);
        }
        if (tid < 256) {
            int tt = tid >> 2, j4 = (tid & 3) * 4;
            *(float4*)(VbS + tt*16 + j4) = *(const float4*)(gv + tbase + (size_t)tt*ROW + j0 + j4);
        }
        if (tid < HD) cpS[tid] = gCp[h*HD + tid];
    }
    __syncthreads();

    for (int c = 0; c < NC; ++c) {
        if (c + 1 < NC) {
            size_t tbase1 = ((size_t)(c+1)*CH*NH + h)*HD;
#pragma unroll
            for (int i = 0; i < 4; ++i) {
                size_t go = tbase1 + (size_t)stt[i]*ROW + sk4[i];
                rKb[i] = *(const float4*)(gg + go);
                rQt[i] = *(const float4*)(gq + go);
                rQr[i] = *(const float4*)(gk + go);
            }
        }

        // ---- D = Vb - Kb@S  and  X = Qt@S (fused) ----
        float2 a0, x0, x1;
        {
            const float* kbr = KbS + t*ST3;
            const float* qtr = QtS + t*ST3;
            a0 = *(const float2*)(VbS + t*16 + jh*2);
            float2 a1 = make_float2(0.f, 0.f);
            x0 = make_float2(0.f, 0.f); x1 = make_float2(0.f, 0.f);
#pragma unroll 8
            for (int k = 0; k < HD; k += 2) {
                float kb0 = kbr[k], kb1 = kbr[k+1];
                float q0 = qtr[k], q1 = qtr[k+1];
                float2 s0 = *(const float2*)(S + k*16 + jh*2);
                float2 s1 = *(const float2*)(S + (k+1)*16 + jh*2);
                a0.x -= kb0*s0.x; a0.y -= kb0*s0.y;
                a1.x -= kb1*s1.x; a1.y -= kb1*s1.y;
                x0.x += q0*s0.x;  x0.y += q0*s0.y;
                x1.x += q1*s1.x;  x1.y += q1*s1.y;
            }
            a0.x += a1.x; a0.y += a1.y;
            x0.x += x1.x; x0.y += x1.y;
            *(float2*)(DS + t*16 + jh*2) = a0;
        }
        __syncthreads();

        // ---- O = X + M@D ----
        {
            float2 o0 = x0, o1 = make_float2(0.f, 0.f);
            const float* mr = MS + t*MT3;
#pragma unroll 8
            for (int s = 0; s < CH; s += 2) {
                float m0 = mr[s], m1 = mr[s+1];
                float2 d0 = *(const float2*)(DS + s*16 + jh*2);
                float2 d1 = *(const float2*)(DS + (s+1)*16 + jh*2);
                o0.x += m0*d0.x; o0.y += m0*d0.y;
                o1.x += m1*d1.x; o1.y += m1*d1.y;
            }
            o0.x += o1.x; o0.y += o1.y;
            *(float2*)(out + ((size_t)(c*CH + t)*NH + h)*HD + j0 + jh*2) = o0;
        }

        // ---- S = cp.*S + Kbar^T@D ----
        {
            float cp = cpS[krow];
            float4* sp4 = (float4*)(S + krow*16 + jq*4);
            float4 sa = *sp4;
            sa.x *= cp; sa.y *= cp; sa.z *= cp; sa.w *= cp;
#pragma unroll 8
            for (int s = 0; s < CH; ++s) {
                float kb = KrS[s*ST3 + krow];
                float4 dv = *(const float4*)(DS + s*16 + jq*4);
                sa.x += kb*dv.x; sa.y += kb*dv.y;
                sa.z += kb*dv.z; sa.w += kb*dv.w;
            }
            *sp4 = sa;
        }
        __syncthreads();

        // ---- commit prefetched chunk c+1 ----
        if (c + 1 < NC) {
            size_t tbase1 = ((size_t)(c+1)*CH*NH + h)*HD;
#pragma unroll
            for (int i = 0; i < 4; ++i) {
                *(float4*)(KbS + stt[i]*ST3 + sk4[i]) = rKb[i];
                *(float4*)(QtS + stt[i]*ST3 + sk4[i]) = rQt[i];
                *(float4*)(KrS + stt[i]*ST3 + sk4[i]) = rQr[i];
            }
            size_t mbase1 = (size_t)((c+1)*NH + h) * CH * CH;
#pragma unroll
            for (int f = tid; f < 1024; f += 512) {
                int tt = f >> 4, s4 = (f & 15) * 4;
                *(float4*)(MS + tt*MT3 + s4) = *(const float4*)(gM + mbase1 + tt*64 + s4);
            }
            if (tid < 256) {
                int tt = tid >> 2, j4 = (tid & 3) * 4;
                *(float4*)(VbS + tt*16 + j4) =
                    *(const float4*)(gv + tbase1 + (size_t)tt*ROW + j0 + j4);
            }
            if (tid < HD) cpS[tid] = gCp[((c+1)*NH+h)*HD + tid];
            __syncthreads();
        }
    }
}

// =========================================================================
extern "C" void kernel_launch(void* const* d_in, const int* in_sizes, int n_in,
                              void* d_out, int out_size)
{
    (void)in_sizes; (void)n_in; (void)out_size;
    const float* qkv  = (const float*)d_in[0];
    const float* fg   = (const float*)d_in[1];
    const float* beta = (const float*)d_in[2];
    const float* cw   = (const float*)d_in[3];
    const float* dtb  = (const float*)d_in[4];
    const float* alog = (const float*)d_in[5];
    float* out = (float*)d_out;

    int smem2 = (3*CH*P2S + CH*65 + 64) * 4;                               // 118,272
    int smem3 = (3*CH*ST3 + CH*MT3 + CH*16*2 + HD + HD*16) * 4;            // 134,912
    cudaFuncSetAttribute(k_phase2, cudaFuncAttributeMaxDynamicSharedMemorySize, smem2);
    cudaFuncSetAttribute(k_phase3, cudaFuncAttributeMaxDynamicSharedMemorySize, smem3);

    k_phase1<<<dim3(NC, NH), 128>>>(qkv, fg, beta, cw, dtb, alog);
    k_phase2<<<dim3(NC, NH), 512, smem2>>>();
    k_phase3<<<dim3(8, NH), 512, smem3>>>(out);
}

// round 11
// speedup vs baseline: 7.2226x; 1.0994x over previous
#include <cuda_runtime.h>
#include <math.h>

#define T_TOK 8192
#define NH 16
#define HD 128
#define CH 64
#define NC 128
#define ROW (NH*HD)   // 2048

// ------------------- device scratch (allocation-free) -------------------
__device__ float gq [T_TOK*ROW];   // q~   (phase12 out)
__device__ float gk [T_TOK*ROW];   // Kbar
__device__ float gv [T_TOK*ROW];   // Vb
__device__ float gg [T_TOK*ROW];   // Kb
__device__ float gM [NC*NH*CH*CH];
__device__ float gCp[NC*NH*HD];

// =========================================================================
// Phase 1+2 fused: conv+SiLU+l2norm+gates straight into smem, then
// cumsum / transform / pair matrices / blocked forward substitution.
// grid (NC, NH), block 512, dyn smem ~149 KB
// =========================================================================
#define P2S 132   // padded row stride (float4-aligned)

__global__ void __launch_bounds__(512) k_phase12(
    const float* __restrict__ qkv, const float* __restrict__ fg,
    const float* __restrict__ beta, const float* __restrict__ cw,
    const float* __restrict__ dtb, const float* __restrict__ alog)
{
    extern __shared__ float sm[];
    float* gcS = sm;               // 64*132 (gates -> cumsum -> ZB = Kb)
    float* qS  = gcS + CH*P2S;     // 64*132 (q -> ZA = Vb)
    float* kS  = qS  + CH*P2S;     // 64*132
    float* vS  = kS  + CH*P2S;     // 64*132
    float* Ls  = vS  + CH*P2S;     // 64*65
    float* bS  = Ls  + CH*65;      // 64

    int c = blockIdx.x, h = blockIdx.y, tid = threadIdx.x;
    int w = tid >> 5, l = tid & 31;
    size_t tbase = ((size_t)c*CH*NH + h)*HD;

    // ================= step A: conv(K=4)+SiLU+l2norm+gates ================
    {
        int tloc0 = w * 4;                    // 4 tokens per warp
        int t0 = c * CH + tloc0;
        int d0 = l * 4;
        int cq = h*HD + d0, ck = ROW + cq, cv = 2*ROW + cq;

        float wq[4][4], wk[4][4], wv[4][4];
#pragma unroll
        for (int e = 0; e < 4; ++e)
#pragma unroll
            for (int j = 0; j < 4; ++j) {
                wq[e][j] = cw[(cq+e)*4 + j];
                wk[e][j] = cw[(ck+e)*4 + j];
                wv[e][j] = cw[(cv+e)*4 + j];
            }
        float ea = expf(alog[h]);
        float dtv[4];
        *(float4*)dtv = *(const float4*)(dtb + h*HD + d0);

        float pq[3][4], pk[3][4], pv[3][4];
#pragma unroll
        for (int j = 0; j < 3; ++j) {
            int ts = t0 - 3 + j;
            if (ts >= 0) {
                const float* row = qkv + (size_t)ts * (3*ROW);
                *(float4*)pq[j] = *(const float4*)(row + cq);
                *(float4*)pk[j] = *(const float4*)(row + ck);
                *(float4*)pv[j] = *(const float4*)(row + cv);
            } else {
#pragma unroll
                for (int e = 0; e < 4; ++e) { pq[j][e]=0.f; pk[j][e]=0.f; pv[j][e]=0.f; }
            }
        }

#pragma unroll
        for (int tt = 0; tt < 4; ++tt) {
            int t = t0 + tt, tloc = tloc0 + tt;
            const float* row = qkv + (size_t)t * (3*ROW);
            float rq[4], rk[4], rv[4], fgv[4];
            *(float4*)rq = *(const float4*)(row + cq);
            *(float4*)rk = *(const float4*)(row + ck);
            *(float4*)rv = *(const float4*)(row + cv);
            *(float4*)fgv = *(const float4*)(fg + (size_t)t*ROW + h*HD + d0);

            float xq[4], xk[4], xv[4];
#pragma unroll
            for (int e = 0; e < 4; ++e) {
                float aq = pq[0][e]*wq[e][0] + pq[1][e]*wq[e][1] + pq[2][e]*wq[e][2] + rq[e]*wq[e][3];
                float ak = pk[0][e]*wk[e][0] + pk[1][e]*wk[e][1] + pk[2][e]*wk[e][2] + rk[e]*wk[e][3];
                float av = pv[0][e]*wv[e][0] + pv[1][e]*wv[e][1] + pv[2][e]*wv[e][2] + rv[e]*wv[e][3];
                xq[e] = aq / (1.f + __expf(-aq));
                xk[e] = ak / (1.f + __expf(-ak));
                xv[e] = av / (1.f + __expf(-av));
            }
#pragma unroll
            for (int j = 0; j < 2; ++j)
#pragma unroll
                for (int e = 0; e < 4; ++e) { pq[j][e]=pq[j+1][e]; pk[j][e]=pk[j+1][e]; pv[j][e]=pv[j+1][e]; }
#pragma unroll
            for (int e = 0; e < 4; ++e) { pq[2][e]=rq[e]; pk[2][e]=rk[e]; pv[2][e]=rv[e]; }

            float sq = xq[0]*xq[0]+xq[1]*xq[1]+xq[2]*xq[2]+xq[3]*xq[3];
            float sk = xk[0]*xk[0]+xk[1]*xk[1]+xk[2]*xk[2]+xk[3]*xk[3];
#pragma unroll
            for (int m = 16; m; m >>= 1) {
                sq += __shfl_xor_sync(~0u, sq, m);
                sk += __shfl_xor_sync(~0u, sk, m);
            }
            float rnq = rsqrtf(sq + 1e-6f) * 0.08838834764831845f; // * D^-1/2
            float rnk = rsqrtf(sk + 1e-6f);

            float oq[4], ok[4], og[4];
#pragma unroll
            for (int e = 0; e < 4; ++e) {
                oq[e] = xq[e] * rnq;
                ok[e] = xk[e] * rnk;
                float gr = fgv[e] + dtv[e];
                float sp = (gr > 20.f) ? gr : log1pf(__expf(gr));
                og[e] = -ea * sp;
            }
            *(float4*)(qS  + tloc*P2S + d0) = *(float4*)oq;
            *(float4*)(kS  + tloc*P2S + d0) = *(float4*)ok;
            *(float4*)(vS  + tloc*P2S + d0) = *(float4*)xv;
            *(float4*)(gcS + tloc*P2S + d0) = *(float4*)og;
            if (l == 0) {
                float bb = beta[t*NH + h];
                bS[tloc] = 1.f / (1.f + __expf(-bb));
            }
        }
    }
    __syncthreads();

    // ---- gc cumsum over t ----
    if (tid < HD) {
        float run = 0.f;
        for (int t = 0; t < CH; ++t) { run += gcS[t*P2S+tid]; gcS[t*P2S+tid] = run; }
    }
    __syncthreads();

    // ---- q~ = q*exp(gc), Kbar = k*exp(gc63-gc), cp = exp(gc63) ----
    for (int i = tid; i < CH*HD; i += 512) {
        int t = i >> 7, k = i & 127;
        float gct = gcS[t*P2S+k];
        float g63 = gcS[63*P2S+k];
        size_t go = tbase + (size_t)t*ROW + k;
        gq[go] = qS[t*P2S+k] * __expf(gct);
        gk[go] = kS[t*P2S+k] * __expf(g63 - gct);
    }
    if (tid < HD) gCp[(c*NH+h)*HD + tid] = __expf(gcS[63*P2S+tid]);

    // ---- pair tiles: warp processes an 8t x 4s tile, lane=(tr,sc) ----
    size_t mbase = (size_t)(c*NH + h) * CH * CH;
    {
        int l5 = tid & 31, tr = l5 >> 2, sc = l5 & 3;
        for (int tile = w; tile < 72; tile += 16) {
            int i = 0;
            while ((i+1)*(i+2) <= tile) ++i;    // tiles before row i = i*(i+1)
            int j = tile - i*(i+1);
            int t = i*8 + tr, s = j*4 + sc;
            const float* gtr = gcS + t*P2S; const float* gsr = gcS + s*P2S;
            const float* ktr = kS  + t*P2S; const float* ksr = kS  + s*P2S;
            const float* qtr = qS  + t*P2S;
            float a = 0.f, m = 0.f;
#pragma unroll 4
            for (int k = 0; k < HD; k += 4) {
                float4 g1 = *(const float4*)(gtr + k);
                float4 g0 = *(const float4*)(gsr + k);
                float4 kt4 = *(const float4*)(ktr + k);
                float4 ks4 = *(const float4*)(ksr + k);
                float4 qt4 = *(const float4*)(qtr + k);
                float e, kv;
                e = __expf(g1.x - g0.x); kv = ks4.x * e; a += kt4.x*kv; m += qt4.x*kv;
                e = __expf(g1.y - g0.y); kv = ks4.y * e; a += kt4.y*kv; m += qt4.y*kv;
                e = __expf(g1.z - g0.z); kv = ks4.z * e; a += kt4.z*kv; m += qt4.z*kv;
                e = __expf(g1.w - g0.w); kv = ks4.w * e; a += kt4.w*kv; m += qt4.w*kv;
            }
            if (s <= t) gM[mbase + t*64 + s] = m;
            if (s <  t) Ls[t*65 + s] = bS[t] * a;
        }
    }
    // zero upper triangle of M
    for (int i = tid; i < 4096; i += 512) {
        int t = i >> 6, s = i & 63;
        if (s > t) gM[mbase + i] = 0.f;
    }
    __syncthreads();

    // ---- RHS in place: ZA(qS) = b*v, ZB(gcS) = b*k*exp(gc) ----
    for (int i = tid; i < CH*HD; i += 512) {
        int t = i >> 7, k = i & 127;
        float bb = bS[t];
        float zb = bb * kS[t*P2S+k] * __expf(gcS[t*P2S+k]);
        qS [t*P2S+k] = bb * vS[t*P2S+k];
        gcS[t*P2S+k] = zb;
    }
    __syncthreads();

    // ---- blocked forward substitution (I+L) Z = RHS ----
#pragma unroll
    for (int ib = 0; ib < 4; ++ib) {
        int i0 = ib * 16;
        if (tid < 256) {
            float* Z = (tid < 128) ? (qS + tid) : (gcS + (tid - 128));
            for (int t = i0+1; t < i0+16; ++t) {
                float acc = 0.f;
                const float* lrow = Ls + t*65;
                for (int s = i0; s < t; ++s) acc += lrow[s] * Z[s*P2S];
                Z[t*P2S] -= acc;
            }
        }
        __syncthreads();
        int rows = 48 - 16*ib;
        if (rows > 0) {
            int slots = rows * 128;
            for (int sl = tid; sl < slots; sl += 512) {
                int t  = i0 + 16 + (sl >> 7);
                int c2 = sl & 127;
                float* Z = (c2 < 64) ? (qS + c2*2) : (gcS + (c2-64)*2);
                float2 acc = make_float2(0.f, 0.f);
                const float* lrow = Ls + t*65 + i0;
#pragma unroll
                for (int s = 0; s < 16; ++s) {
                    float lv = lrow[s];
                    float2 zv = *(const float2*)(Z + (i0+s)*P2S);
                    acc.x += lv*zv.x; acc.y += lv*zv.y;
                }
                float2 zt = *(float2*)(Z + t*P2S);
                zt.x -= acc.x; zt.y -= acc.y;
                *(float2*)(Z + t*P2S) = zt;
            }
        }
        __syncthreads();
    }

    // ---- write out: Vb -> gv, Kb -> gg ----
    for (int i = tid; i < CH*HD; i += 512) {
        int t = i >> 7, k = i & 127;
        size_t go = tbase + (size_t)t*ROW + k;
        gv[go] = qS [t*P2S+k];
        gg[go] = gcS[t*P2S+k];
    }
}

// =========================================================================
// Phase 3: sequential chunk scan, 2 syncs/chunk, all staging register-
// prefetched and committed as pure STS overlapped with compute.
// grid (8, NH), block 512.
// Per chunk: [D = Vb - Kb@S ; X = Qt@S] ; sync1 ;
//            commit{Kb,Qt,Vb} + O = X + M@D + S = cp.*S + Kbar^T@D ; sync2 ;
//            commit{Kr,M,cp} runs concurrent with next fused pass.
// =========================================================================
#define ST3 132          // k-row stride (float4-aligned)
#define MT3 68           // M row stride

__global__ void __launch_bounds__(512) k_phase3(float* __restrict__ out)
{
    extern __shared__ float sm[];
    float* KbS = sm;                 // 64*132
    float* QtS = KbS + CH*ST3;
    float* KrS = QtS + CH*ST3;
    float* MS  = KrS + CH*ST3;       // 64*68
    float* VbS = MS  + CH*MT3;       // 64*16
    float* DS  = VbS + CH*16;        // 64*16
    float* cpS = DS  + CH*16;        // 128
    float* S   = cpS + HD;           // 128*16

    int h = blockIdx.y, j0 = blockIdx.x * 16, tid = threadIdx.x;
    int t  = tid >> 3, jh = tid & 7;        // D/O mapping: j = jh*2
    int krow = tid >> 2, jq = tid & 3;      // S-update mapping

    float4 rKb[4], rQt[4], rKr[4], rM[2], rVb;
    float rCp = 0.f;
    int stt[4], sk4[4];
#pragma unroll
    for (int i = 0; i < 4; ++i) {
        int idx = tid + i*512;
        stt[i] = idx >> 5; sk4[i] = (idx & 31) * 4;
    }
    int mtt[2], ms4[2];
#pragma unroll
    for (int i = 0; i < 2; ++i) {
        int f = tid + i*512;
        mtt[i] = f >> 4; ms4[i] = (f & 15) * 4;
    }
    int vtt = tid >> 2, vj4 = (tid & 3) * 4;

    for (int i = tid; i < HD*16; i += 512) S[i] = 0.f;

    // ---- prologue: load + commit chunk 0 ----
    {
        size_t tbase = ((size_t)h)*HD;
#pragma unroll
        for (int i = 0; i < 4; ++i) {
            size_t go = tbase + (size_t)stt[i]*ROW + sk4[i];
            *(float4*)(KbS + stt[i]*ST3 + sk4[i]) = *(const float4*)(gg + go);
            *(float4*)(QtS + stt[i]*ST3 + sk4[i]) = *(const float4*)(gq + go);
            *(float4*)(KrS + stt[i]*ST3 + sk4[i]) = *(const float4*)(gk + go);
        }
#pragma unroll
        for (int i = 0; i < 2; ++i)
            *(float4*)(MS + mtt[i]*MT3 + ms4[i]) =
                *(const float4*)(gM + (size_t)h*CH*CH + mtt[i]*64 + ms4[i]);
        if (tid < 256)
            *(float4*)(VbS + vtt*16 + vj4) =
                *(const float4*)(gv + tbase + (size_t)vtt*ROW + j0 + vj4);
        if (tid < HD) cpS[tid] = gCp[h*HD + tid];
    }
    __syncthreads();

    for (int c = 0; c < NC; ++c) {
        // ---- issue ALL prefetch loads for chunk c+1 (hidden under fused) ----
        if (c + 1 < NC) {
            size_t tbase1 = ((size_t)(c+1)*CH*NH + h)*HD;
#pragma unroll
            for (int i = 0; i < 4; ++i) {
                size_t go = tbase1 + (size_t)stt[i]*ROW + sk4[i];
                rKb[i] = *(const float4*)(gg + go);
                rQt[i] = *(const float4*)(gq + go);
                rKr[i] = *(const float4*)(gk + go);
            }
            size_t mbase1 = (size_t)((c+1)*NH + h) * CH * CH;
#pragma unroll
            for (int i = 0; i < 2; ++i)
                rM[i] = *(const float4*)(gM + mbase1 + mtt[i]*64 + ms4[i]);
            if (tid < 256)
                rVb = *(const float4*)(gv + tbase1 + (size_t)vtt*ROW + j0 + vj4);
            if (tid < HD) rCp = gCp[((c+1)*NH+h)*HD + tid];
        }

        // ---- D = Vb - Kb@S  and  X = Qt@S (fused) ----
        float2 a0, x0, x1;
        {
            const float* kbr = KbS + t*ST3;
            const float* qtr = QtS + t*ST3;
            a0 = *(const float2*)(VbS + t*16 + jh*2);
            float2 a1 = make_float2(0.f, 0.f);
            x0 = make_float2(0.f, 0.f); x1 = make_float2(0.f, 0.f);
#pragma unroll 8
            for (int k = 0; k < HD; k += 2) {
                float kb0 = kbr[k], kb1 = kbr[k+1];
                float q0 = qtr[k], q1 = qtr[k+1];
                float2 s0 = *(const float2*)(S + k*16 + jh*2);
                float2 s1 = *(const float2*)(S + (k+1)*16 + jh*2);
                a0.x -= kb0*s0.x; a0.y -= kb0*s0.y;
                a1.x -= kb1*s1.x; a1.y -= kb1*s1.y;
                x0.x += q0*s0.x;  x0.y += q0*s0.y;
                x1.x += q1*s1.x;  x1.y += q1*s1.y;
            }
            a0.x += a1.x; a0.y += a1.y;
            x0.x += x1.x; x0.y += x1.y;
            *(float2*)(DS + t*16 + jh*2) = a0;
        }
        __syncthreads();   // sync1: DS ready; fused pass done with KbS/QtS/VbS/S

        // ---- group1 commit (c+1): KbS, QtS, VbS — overlapped with O/S-update ----
        if (c + 1 < NC) {
#pragma unroll
            for (int i = 0; i < 4; ++i) {
                *(float4*)(KbS + stt[i]*ST3 + sk4[i]) = rKb[i];
                *(float4*)(QtS + stt[i]*ST3 + sk4[i]) = rQt[i];
            }
            if (tid < 256) *(float4*)(VbS + vtt*16 + vj4) = rVb;
        }

        // ---- O = X + M@D ----
        {
            float2 o0 = x0, o1 = make_float2(0.f, 0.f);
            const float* mr = MS + t*MT3;
#pragma unroll 8
            for (int s = 0; s < CH; s += 2) {
                float m0 = mr[s], m1 = mr[s+1];
                float2 d0 = *(const float2*)(DS + s*16 + jh*2);
                float2 d1 = *(const float2*)(DS + (s+1)*16 + jh*2);
                o0.x += m0*d0.x; o0.y += m0*d0.y;
                o1.x += m1*d1.x; o1.y += m1*d1.y;
            }
            o0.x += o1.x; o0.y += o1.y;
            *(float2*)(out + ((size_t)(c*CH + t)*NH + h)*HD + j0 + jh*2) = o0;
        }

        // ---- S = cp.*S + Kbar^T@D ----
        {
            float cp = cpS[krow];
            float4* sp4 = (float4*)(S + krow*16 + jq*4);
            float4 sa = *sp4;
            sa.x *= cp; sa.y *= cp; sa.z *= cp; sa.w *= cp;
#pragma unroll 8
            for (int s = 0; s < CH; ++s) {
                float kb = KrS[s*ST3 + krow];
                float4 dv = *(const float4*)(DS + s*16 + jq*4);
                sa.x += kb*dv.x; sa.y += kb*dv.y;
                sa.z += kb*dv.z; sa.w += kb*dv.w;
            }
            *sp4 = sa;
        }
        __syncthreads();   // sync2: S updated; KrS/MS/cpS free to overwrite

        // ---- group2 commit (c+1): KrS, MS, cpS — overlaps next fused pass ----
        if (c + 1 < NC) {
#pragma unroll
            for (int i = 0; i < 4; ++i)
                *(float4*)(KrS + stt[i]*ST3 + sk4[i]) = rKr[i];
#pragma unroll
            for (int i = 0; i < 2; ++i)
                *(float4*)(MS + mtt[i]*MT3 + ms4[i]) = rM[i];
            if (tid < HD) cpS[tid] = rCp;
        }
        // NOTE: no sync here. Next fused pass reads only KbS/QtS/VbS/S (group1,
        // separated by sync2) — group2 arrays aren't read until after next sync1.
        // But next sync1 is preceded by reads of group2 arrays?  No: O/S-update
        // (which read MS/KrS/cpS) come after next sync1, which follows this
        // commit on every thread — ordering is: commit -> fused -> sync1 -> read.
    }
}

// =========================================================================
extern "C" void kernel_launch(void* const* d_in, const int* in_sizes, int n_in,
                              void* d_out, int out_size)
{
    (void)in_sizes; (void)n_in; (void)out_size;
    const float* qkv  = (const float*)d_in[0];
    const float* fg   = (const float*)d_in[1];
    const float* beta = (const float*)d_in[2];
    const float* cw   = (const float*)d_in[3];
    const float* dtb  = (const float*)d_in[4];
    const float* alog = (const float*)d_in[5];
    float* out = (float*)d_out;

    int smem12 = (4*CH*P2S + CH*65 + 64) * 4;                              // 152,064
    int smem3  = (3*CH*ST3 + CH*MT3 + CH*16*2 + HD + HD*16) * 4;           // 134,912
    cudaFuncSetAttribute(k_phase12, cudaFuncAttributeMaxDynamicSharedMemorySize, smem12);
    cudaFuncSetAttribute(k_phase3,  cudaFuncAttributeMaxDynamicSharedMemorySize, smem3);

    k_phase12<<<dim3(NC, NH), 512, smem12>>>(qkv, fg, beta, cw, dtb, alog);
    k_phase3<<<dim3(8, NH), 512, smem3>>>(out);
}